// round 16
// baseline (speedup 1.0000x reference)
#include <cuda_runtime.h>
#include <cuda_fp16.h>
#include <cstdint>

#define NN 40000
#define EE 640000
#define DIM 128
#define CAP 96    // per-node bucket capacity (max degree ~45 for E/N=16)
#define NTILE 313 // ceil(NN/128)

// Scratch (static device globals — no allocation)
__device__ __half g_hs[NN * DIM];      // h @ W (fp16; pre-scaled by dinv[row] on layers 1,2)
__device__ __half g_h[NN * DIM];       // layer output (fp16)
__device__ __half g_wt[3 * DIM * DIM]; // W^T fp16, [layer][n][k]
__device__ int    g_cnt[NN];
__device__ int    g_ssrc[NN * CAP];    // per-node edge-source buckets
__device__ int    g_bar_cnt;           // barrier arrivals (self-resetting)
__device__ volatile int g_bar_gen;     // barrier generation (monotonic, replay-safe)

#define HSTR 68   // smem words per row (64 data + 4 pad; bank bijection)
#define GEMM_SMEM (2 * 128 * HSTR * 4)

// ---------------- grid-wide barrier (sense-reversing, L1-invalidating) ----------------

__device__ __forceinline__ void grid_bar(int G) {
    __threadfence();                    // release: publish this thread's writes
    __syncthreads();                    // all block threads have fenced
    if (threadIdx.x == 0) {
        int gen = g_bar_gen;
        if (atomicAdd(&g_bar_cnt, 1) == G - 1) {
            g_bar_cnt = 0;
            __threadfence();
            g_bar_gen = gen + 1;
        } else {
            while (g_bar_gen == gen) { }
        }
    }
    __syncthreads();
    __threadfence();                    // acquire: CCTL.IVALL so loads see fresh data
}

// ---------------- device: one 128-row GEMM tile (HMMA m16n8k16) ----------------

__device__ void gemm_tile(uint32_t* sm, const float* __restrict__ Ax,
                          int layer, int r0, bool fromH, bool scale, int tid) {
    const __half* __restrict__ Wt = g_wt + layer * DIM * DIM;
    uint32_t* sA  = sm;               // [128 m][68] half2 words; reused as epilogue buffer
    uint32_t* sWt = sm + 128 * HSTR;  // [128 n][68] half2 words; W^T

    __syncthreads();                  // guard smem reuse across tiles/phases

    if (fromH) {
        #pragma unroll
        for (int i = tid; i < 128 * 16; i += 256) {
            int r = i >> 4, q = i & 15;
            int rr = min(r0 + r, NN - 1);
            uint4 v = *(const uint4*)&g_h[rr * DIM + q * 8];
            *(uint4*)((__half*)sA + r * 2 * HSTR + q * 8) = v;
        }
    } else {
        #pragma unroll
        for (int i = tid; i < 128 * 32; i += 256) {
            int r = i >> 5, c4 = (i & 31) << 2;
            int rr = min(r0 + r, NN - 1);
            float4 v = *(const float4*)&Ax[rr * DIM + c4];
            __half2 h0 = __floats2half2_rn(v.x, v.y);
            __half2 h1 = __floats2half2_rn(v.z, v.w);
            uint2 u; u.x = *(uint32_t*)&h0; u.y = *(uint32_t*)&h1;
            *(uint2*)&sA[r * HSTR + (c4 >> 1)] = u;
        }
    }
    #pragma unroll
    for (int i = tid; i < 128 * 16; i += 256) {
        int n = i >> 4, q = i & 15;
        uint4 v = *(const uint4*)&Wt[n * DIM + q * 8];
        *(uint4*)((__half*)sWt + n * 2 * HSTR + q * 8) = v;
    }
    __syncthreads();

    int warp = tid >> 5, lane = tid & 31;
    int g = lane >> 2, tg = lane & 3;
    int mw = (warp & 3) * 32;
    int nw = (warp >> 2) * 64;

    float c[2][8][4];
    #pragma unroll
    for (int mt = 0; mt < 2; mt++)
        #pragma unroll
        for (int nt = 0; nt < 8; nt++) {
            c[mt][nt][0] = 0.f; c[mt][nt][1] = 0.f;
            c[mt][nt][2] = 0.f; c[mt][nt][3] = 0.f;
        }

    #pragma unroll
    for (int kt = 0; kt < 8; kt++) {
        int kw = kt * 8;
        uint32_t a[2][4];
        #pragma unroll
        for (int mt = 0; mt < 2; mt++) {
            int rb = mw + mt * 16;
            a[mt][0] = sA[(rb + g) * HSTR + kw + tg];
            a[mt][1] = sA[(rb + g + 8) * HSTR + kw + tg];
            a[mt][2] = sA[(rb + g) * HSTR + kw + 4 + tg];
            a[mt][3] = sA[(rb + g + 8) * HSTR + kw + 4 + tg];
        }
        #pragma unroll
        for (int nt = 0; nt < 8; nt++) {
            int nr = nw + nt * 8 + g;
            uint32_t b0 = sWt[nr * HSTR + kw + tg];
            uint32_t b1 = sWt[nr * HSTR + kw + 4 + tg];
            #pragma unroll
            for (int mt = 0; mt < 2; mt++) {
                asm volatile(
                    "mma.sync.aligned.m16n8k16.row.col.f32.f16.f16.f32 "
                    "{%0,%1,%2,%3}, {%4,%5,%6,%7}, {%8,%9}, {%0,%1,%2,%3};\n"
                    : "+f"(c[mt][nt][0]), "+f"(c[mt][nt][1]),
                      "+f"(c[mt][nt][2]), "+f"(c[mt][nt][3])
                    : "r"(a[mt][0]), "r"(a[mt][1]), "r"(a[mt][2]), "r"(a[mt][3]),
                      "r"(b0), "r"(b1));
            }
        }
    }

    // Epilogue: dinv-scale, pack half2 into sA (conflict-free), then uint4 out
    __syncthreads();
    #pragma unroll
    for (int mt = 0; mt < 2; mt++) {
        int rb = mw + mt * 16;
        int row0 = r0 + rb + g;
        int row1 = row0 + 8;
        float d0 = 1.f, d1 = 1.f;
        if (scale) {
            d0 = (row0 < NN) ? rsqrtf(1.0f + (float)g_cnt[row0]) : 0.f;
            d1 = (row1 < NN) ? rsqrtf(1.0f + (float)g_cnt[row1]) : 0.f;
        }
        #pragma unroll
        for (int nt = 0; nt < 8; nt++) {
            int wofs = (nw >> 1) + nt * 4 + tg;
            __half2 o0 = __floats2half2_rn(c[mt][nt][0] * d0, c[mt][nt][1] * d0);
            __half2 o1 = __floats2half2_rn(c[mt][nt][2] * d1, c[mt][nt][3] * d1);
            sA[(rb + g) * HSTR + wofs] = *(uint32_t*)&o0;
            sA[(rb + g + 8) * HSTR + wofs] = *(uint32_t*)&o1;
        }
    }
    __syncthreads();
    #pragma unroll
    for (int i = tid; i < 128 * 16; i += 256) {
        int r = i >> 4, q = i & 15;
        int row = r0 + r;
        if (row < NN) {
            uint4 v = *(const uint4*)&sA[r * HSTR + q * 4];
            *(uint4*)&g_hs[row * DIM + q * 8] = v;
        }
    }
}

// ---------------- device: aggregation phase (strided over nodes) ----------------

__device__ void agg_phase(int b, int tid, int G,
                          const float* __restrict__ bias, bool scale_src, bool fin,
                          const float* __restrict__ lw, const float* __restrict__ lb,
                          float* __restrict__ out) {
    int lane = tid & 31;
    int l4 = lane * 4;
    const __half* hs_l = &g_hs[l4];
    float4 bb = *(const float4*)&bias[l4];
    float4 lwv = fin ? *(const float4*)&lw[l4] : make_float4(0.f, 0.f, 0.f, 0.f);
    float lbv = fin ? lb[0] : 0.f;
    int gw0 = b * 8 + (tid >> 5);
    int stride = G * 8;

    for (int w = gw0; w < NN; w += stride) {
        const int* ss = &g_ssrc[w * CAP];
        int n = min(g_cnt[w], CAP);
        float4 acc = make_float4(0.f, 0.f, 0.f, 0.f);

        for (int base = 0; base < n; base += 32) {
            int cnt = min(32, n - base);
            int idx = (lane < cnt) ? ss[base + lane] : 0;
            float dv = 1.f;
            if (scale_src) dv = (lane < cnt) ? rsqrtf(1.0f + (float)g_cnt[idx]) : 1.f;

            #pragma unroll 4
            for (int j = 0; j < cnt; j++) {
                int s = __shfl_sync(0xffffffffu, idx, j);
                uint2 rv = *(const uint2*)&hs_l[s * DIM];
                float2 f0 = __half22float2(*(__half2*)&rv.x);
                float2 f1 = __half22float2(*(__half2*)&rv.y);
                float sc = scale_src ? __shfl_sync(0xffffffffu, dv, j) : 1.f;
                acc.x = fmaf(f0.x, sc, acc.x);
                acc.y = fmaf(f0.y, sc, acc.y);
                acc.z = fmaf(f1.x, sc, acc.z);
                acc.w = fmaf(f1.y, sc, acc.w);
            }
        }

        float di = rsqrtf(1.0f + (float)g_cnt[w]);
        uint2 sv = *(const uint2*)&hs_l[w * DIM];
        float2 s0 = __half22float2(*(__half2*)&sv.x);
        float2 s1 = __half22float2(*(__half2*)&sv.y);
        float selfsc = scale_src ? di : 1.f;

        float4 r;
        r.x = fmaxf(di * (acc.x + s0.x * selfsc) + bb.x, 0.f);
        r.y = fmaxf(di * (acc.y + s0.y * selfsc) + bb.y, 0.f);
        r.z = fmaxf(di * (acc.z + s1.x * selfsc) + bb.z, 0.f);
        r.w = fmaxf(di * (acc.w + s1.y * selfsc) + bb.w, 0.f);

        if (fin) {
            float p = r.x * lwv.x + r.y * lwv.y + r.z * lwv.z + r.w * lwv.w;
            #pragma unroll
            for (int o = 16; o > 0; o >>= 1) p += __shfl_xor_sync(0xffffffffu, p, o);
            if (lane == 0) out[w] = p + lbv;
        } else {
            __half2 h0 = __floats2half2_rn(r.x, r.y);
            __half2 h1 = __floats2half2_rn(r.z, r.w);
            uint2 u; u.x = *(uint32_t*)&h0; u.y = *(uint32_t*)&h1;
            *(uint2*)&g_h[w * DIM + l4] = u;
        }
    }
}

// ---------------- the single persistent kernel ----------------

__global__ void __launch_bounds__(256, 2)
fused_k(int G,
        const float* __restrict__ x, const int* __restrict__ src, const int* __restrict__ dst,
        const float* __restrict__ W0, const float* __restrict__ b0,
        const float* __restrict__ W1, const float* __restrict__ b1,
        const float* __restrict__ W2, const float* __restrict__ b2,
        const float* __restrict__ lw, const float* __restrict__ lb,
        float* __restrict__ out)
{
    extern __shared__ uint32_t sm[];
    int b = blockIdx.x, tid = threadIdx.x;

    // Phase A: zero counters + transpose/convert all 3 weight matrices
    for (int i = b * 256 + tid; i < NN; i += G * 256) g_cnt[i] = 0;
    if (b < 48) {
        int layer = b / 16, t16 = b % 16;
        const float* W = (layer == 0) ? W0 : ((layer == 1) ? W1 : W2);
        int n0 = (t16 & 3) * 32, k0 = (t16 >> 2) * 32;
        float* tb = (float*)sm;                  // 32x33 transpose buffer
        int tx = tid & 31, ty = tid >> 5;
        for (int r = ty; r < 32; r += 8)
            tb[r * 33 + tx] = W[(k0 + r) * DIM + n0 + tx];
        __syncthreads();
        __half* op = g_wt + layer * DIM * DIM;
        for (int r = ty; r < 32; r += 8)
            op[(n0 + r) * DIM + k0 + tx] = __float2half_rn(tb[tx * 33 + r]);
    }
    grid_bar(G);

    // Phase B: bucket placement (2 edges/thread) + layer-0 GEMM
    for (int e2 = b * 256 + tid; e2 < EE / 2; e2 += G * 256) {
        int2 d = ((const int2*)dst)[e2];
        int2 s = ((const int2*)src)[e2];
        int p0 = atomicAdd(&g_cnt[d.x], 1);
        int p1 = atomicAdd(&g_cnt[d.y], 1);
        if (p0 < CAP) g_ssrc[d.x * CAP + p0] = s.x;
        if (p1 < CAP) g_ssrc[d.y * CAP + p1] = s.y;
    }
    for (int tile = b; tile < NTILE; tile += G)
        gemm_tile(sm, x, 0, tile * 128, false, false, tid);
    grid_bar(G);

    // Phase C: agg layer 0 (src-side dinv)
    agg_phase(b, tid, G, b0, true, false, nullptr, nullptr, nullptr);
    grid_bar(G);

    // Phase D: gemm layer 1
    for (int tile = b; tile < NTILE; tile += G)
        gemm_tile(sm, nullptr, 1, tile * 128, true, true, tid);
    grid_bar(G);

    // Phase E: agg layer 1
    agg_phase(b, tid, G, b1, false, false, nullptr, nullptr, nullptr);
    grid_bar(G);

    // Phase F: gemm layer 2
    for (int tile = b; tile < NTILE; tile += G)
        gemm_tile(sm, nullptr, 2, tile * 128, true, true, tid);
    grid_bar(G);

    // Phase G: agg layer 2 + final projection
    agg_phase(b, tid, G, b2, false, true, lw, lb, out);
}

// ---------------- launch ----------------

extern "C" void kernel_launch(void* const* d_in, const int* in_sizes, int n_in,
                              void* d_out, int out_size) {
    const float* x  = (const float*)d_in[0];
    const int*   ei = (const int*)d_in[1];
    const int*   src = ei;
    const int*   dst = ei + EE;
    const float* W0 = (const float*)d_in[2];
    const float* b0 = (const float*)d_in[3];
    const float* W1 = (const float*)d_in[4];
    const float* b1 = (const float*)d_in[5];
    const float* W2 = (const float*)d_in[6];
    const float* b2 = (const float*)d_in[7];
    const float* lw = (const float*)d_in[8];
    const float* lb = (const float*)d_in[9];
    float* out = (float*)d_out;

    static int G = 0;
    if (G == 0) {   // pre-capture correctness call: query once
        cudaFuncSetAttribute(fused_k, cudaFuncAttributeMaxDynamicSharedMemorySize, GEMM_SMEM);
        int nsm = 0, occ = 0;
        cudaDeviceGetAttribute(&nsm, cudaDevAttrMultiProcessorCount, 0);
        cudaOccupancyMaxActiveBlocksPerMultiprocessor(&occ, fused_k, 256, GEMM_SMEM);
        if (nsm <= 0) nsm = 148;
        if (occ < 1) occ = 1;
        if (occ > 2) occ = 2;
        G = nsm * occ;
    }

    fused_k<<<G, 256, GEMM_SMEM>>>(G, x, src, dst, W0, b0, W1, b1, W2, b2, lw, lb, out);
}

// round 17
// speedup vs baseline: 1.7169x; 1.7169x over previous
#include <cuda_runtime.h>
#include <cuda_fp16.h>
#include <cstdint>

#define NN 40000
#define EE 640000
#define DIM 128
#define CAP 96    // per-node bucket capacity (max degree ~45 for E/N=16)

// Scratch (static device globals — no allocation; zero-initialized at load)
__device__ __half g_hs[NN * DIM];      // h @ W (fp16; pre-scaled by dinv[row] on layers 1,2)
__device__ __half g_h[NN * DIM];       // layer output (fp16)
__device__ __half g_wt[3 * DIM * DIM]; // W^T fp16, [layer][n][k]
__device__ int    g_cnt[NN];           // degree counters (zeroed by agg2 each call)
__device__ int    g_ssrc[NN * CAP];    // per-node edge-source buckets

// ---------------- one-time W transpose+convert, all 3 layers in one launch ----------------

__global__ void wconv_k(const float* __restrict__ W0, const float* __restrict__ W1,
                        const float* __restrict__ W2) {
    __shared__ float t[32][33];
    int layer = blockIdx.x >> 4, t16 = blockIdx.x & 15;
    const float* W = (layer == 0) ? W0 : ((layer == 1) ? W1 : W2);
    __half* out = g_wt + layer * DIM * DIM;
    int n0 = (t16 & 3) * 32, k0 = (t16 >> 2) * 32;
    int tx = threadIdx.x & 31, ty = threadIdx.x >> 5;
    for (int r = ty; r < 32; r += 8)
        t[r][tx] = W[(k0 + r) * DIM + n0 + tx];
    __syncthreads();
    for (int r = ty; r < 32; r += 8)
        out[(n0 + r) * DIM + k0 + tx] = __float2half_rn(t[tx][r]);
}

// ---------------- bucket build: counting + placement fused, 4 edges/thread ----------------

__global__ void place_k(const int* __restrict__ src, const int* __restrict__ dst) {
    int e4 = blockIdx.x * blockDim.x + threadIdx.x;
    if (e4 * 4 < EE) {
        int4 d = *(const int4*)&dst[e4 * 4];
        int4 s = *(const int4*)&src[e4 * 4];
        int p0 = atomicAdd(&g_cnt[d.x], 1);
        int p1 = atomicAdd(&g_cnt[d.y], 1);
        int p2 = atomicAdd(&g_cnt[d.z], 1);
        int p3 = atomicAdd(&g_cnt[d.w], 1);
        if (p0 < CAP) g_ssrc[d.x * CAP + p0] = s.x;
        if (p1 < CAP) g_ssrc[d.y * CAP + p1] = s.y;
        if (p2 < CAP) g_ssrc[d.z * CAP + p2] = s.z;
        if (p3 < CAP) g_ssrc[d.w * CAP + p3] = s.w;
    }
}

// ---------------- fp16 HMMA GEMM: g_hs(fp16) = (A @ W) [* dinv[row] if SCALE] ----------------
// W^T fp16 precomputed in g_wt; A is fp32 x (layer 0) or fp16 g_h (layers 1,2).
// Stride 68 words: fragment LDS bank = 4g + tg (bijection) -> conflict-free.
// Warp tile 32m x 64n (8 warps = 4m x 2n): 192 LDS + 128 MMA per warp.
// Epilogue: dinv-scaled half2 accumulators staged to smem, coalesced uint4 out.

#define HSTR 68   // words per row (64 data + 4 pad)
#define GEMM_SMEM (2 * 128 * HSTR * 4)

template <bool FROM_H, bool SCALE>
__global__ void gemm_tc(const float* __restrict__ Ax, int layer) {
    const __half* __restrict__ Wt = g_wt + layer * DIM * DIM;
    extern __shared__ uint32_t sm[];
    uint32_t* sA  = sm;               // [128 m][68] half2 words; reused as epilogue buffer
    uint32_t* sWt = sm + 128 * HSTR;  // [128 n][68] half2 words; W^T

    int tid = threadIdx.x;
    int r0 = blockIdx.x * 128;

    if (FROM_H) {
        #pragma unroll
        for (int i = tid; i < 128 * 16; i += 256) {
            int r = i >> 4, q = i & 15;
            int rr = min(r0 + r, NN - 1);
            uint4 v = *(const uint4*)&g_h[rr * DIM + q * 8];
            *(uint4*)((__half*)sA + r * 2 * HSTR + q * 8) = v;
        }
    } else {
        #pragma unroll
        for (int i = tid; i < 128 * 32; i += 256) {
            int r = i >> 5, c4 = (i & 31) << 2;
            int rr = min(r0 + r, NN - 1);
            float4 v = *(const float4*)&Ax[rr * DIM + c4];
            __half2 h0 = __floats2half2_rn(v.x, v.y);
            __half2 h1 = __floats2half2_rn(v.z, v.w);
            uint2 u; u.x = *(uint32_t*)&h0; u.y = *(uint32_t*)&h1;
            *(uint2*)&sA[r * HSTR + (c4 >> 1)] = u;
        }
    }
    #pragma unroll
    for (int i = tid; i < 128 * 16; i += 256) {
        int n = i >> 4, q = i & 15;
        uint4 v = *(const uint4*)&Wt[n * DIM + q * 8];
        *(uint4*)((__half*)sWt + n * 2 * HSTR + q * 8) = v;
    }
    __syncthreads();

    int warp = tid >> 5, lane = tid & 31;
    int g = lane >> 2, tg = lane & 3;
    int mw = (warp & 3) * 32;
    int nw = (warp >> 2) * 64;

    float c[2][8][4];
    #pragma unroll
    for (int mt = 0; mt < 2; mt++)
        #pragma unroll
        for (int nt = 0; nt < 8; nt++) {
            c[mt][nt][0] = 0.f; c[mt][nt][1] = 0.f;
            c[mt][nt][2] = 0.f; c[mt][nt][3] = 0.f;
        }

    #pragma unroll
    for (int kt = 0; kt < 8; kt++) {
        int kw = kt * 8;
        uint32_t a[2][4];
        #pragma unroll
        for (int mt = 0; mt < 2; mt++) {
            int rb = mw + mt * 16;
            a[mt][0] = sA[(rb + g) * HSTR + kw + tg];
            a[mt][1] = sA[(rb + g + 8) * HSTR + kw + tg];
            a[mt][2] = sA[(rb + g) * HSTR + kw + 4 + tg];
            a[mt][3] = sA[(rb + g + 8) * HSTR + kw + 4 + tg];
        }
        #pragma unroll
        for (int nt = 0; nt < 8; nt++) {
            int nr = nw + nt * 8 + g;
            uint32_t b0 = sWt[nr * HSTR + kw + tg];
            uint32_t b1 = sWt[nr * HSTR + kw + 4 + tg];
            #pragma unroll
            for (int mt = 0; mt < 2; mt++) {
                asm volatile(
                    "mma.sync.aligned.m16n8k16.row.col.f32.f16.f16.f32 "
                    "{%0,%1,%2,%3}, {%4,%5,%6,%7}, {%8,%9}, {%0,%1,%2,%3};\n"
                    : "+f"(c[mt][nt][0]), "+f"(c[mt][nt][1]),
                      "+f"(c[mt][nt][2]), "+f"(c[mt][nt][3])
                    : "r"(a[mt][0]), "r"(a[mt][1]), "r"(a[mt][2]), "r"(a[mt][3]),
                      "r"(b0), "r"(b1));
            }
        }
    }

    __syncthreads();
    #pragma unroll
    for (int mt = 0; mt < 2; mt++) {
        int rb = mw + mt * 16;
        int row0 = r0 + rb + g;
        int row1 = row0 + 8;
        float d0 = 1.f, d1 = 1.f;
        if (SCALE) {   // layer 0 must NOT touch g_cnt (CSR build runs concurrently)
            d0 = (row0 < NN) ? rsqrtf(1.0f + (float)g_cnt[row0]) : 0.f;
            d1 = (row1 < NN) ? rsqrtf(1.0f + (float)g_cnt[row1]) : 0.f;
        }
        #pragma unroll
        for (int nt = 0; nt < 8; nt++) {
            int wofs = (nw >> 1) + nt * 4 + tg;
            __half2 o0 = __floats2half2_rn(c[mt][nt][0] * d0, c[mt][nt][1] * d0);
            __half2 o1 = __floats2half2_rn(c[mt][nt][2] * d1, c[mt][nt][3] * d1);
            sA[(rb + g) * HSTR + wofs] = *(uint32_t*)&o0;
            sA[(rb + g + 8) * HSTR + wofs] = *(uint32_t*)&o1;
        }
    }
    __syncthreads();
    #pragma unroll
    for (int i = tid; i < 128 * 16; i += 256) {
        int r = i >> 4, q = i & 15;
        int row = r0 + r;
        if (row < NN) {
            uint4 v = *(const uint4*)&sA[r * HSTR + q * 4];
            *(uint4*)&g_hs[row * DIM + q * 8] = v;
        }
    }
}

// ---------------- Aggregation: one warp per node, fp16 gather, fp32 accum ----------------
// FINAL also zeroes g_cnt[w] after last use -> next call starts with cnt=0
// (device globals are zero-initialized, so call 1 is consistent too).

template <bool SCALE_SRC, bool FINAL>
__global__ void agg_k(const float* __restrict__ bias,
                      const float* __restrict__ lw,
                      const float* __restrict__ lb,
                      float* __restrict__ out) {
    int w = (blockIdx.x * blockDim.x + threadIdx.x) >> 5;
    int lane = threadIdx.x & 31;
    if (w >= NN) return;
    int l4 = lane * 4;
    const __half* hs_l = &g_hs[l4];

    const int* ss = &g_ssrc[w * CAP];
    int cw = g_cnt[w];
    int n = min(cw, CAP);
    float4 acc = make_float4(0.f, 0.f, 0.f, 0.f);

    for (int base = 0; base < n; base += 32) {
        int cnt = min(32, n - base);
        int idx = (lane < cnt) ? ss[base + lane] : 0;
        float dv = 1.f;
        if (SCALE_SRC) dv = (lane < cnt) ? rsqrtf(1.0f + (float)g_cnt[idx]) : 1.f;

        #pragma unroll 4
        for (int j = 0; j < cnt; j++) {
            int s = __shfl_sync(0xffffffffu, idx, j);
            uint2 rv = *(const uint2*)&hs_l[s * DIM];
            float2 f0 = __half22float2(*(__half2*)&rv.x);
            float2 f1 = __half22float2(*(__half2*)&rv.y);
            float sc = SCALE_SRC ? __shfl_sync(0xffffffffu, dv, j) : 1.f;
            acc.x = fmaf(f0.x, sc, acc.x);
            acc.y = fmaf(f0.y, sc, acc.y);
            acc.z = fmaf(f1.x, sc, acc.z);
            acc.w = fmaf(f1.y, sc, acc.w);
        }
    }

    float di = rsqrtf(1.0f + (float)cw);
    if (FINAL && lane == 0) g_cnt[w] = 0;   // reset for next call (after last read)
    uint2 sv = *(const uint2*)&hs_l[w * DIM];
    float2 s0 = __half22float2(*(__half2*)&sv.x);
    float2 s1 = __half22float2(*(__half2*)&sv.y);
    float selfsc = SCALE_SRC ? di : 1.f;
    float4 bb = *(const float4*)&bias[l4];

    float4 r;
    r.x = fmaxf(di * (acc.x + s0.x * selfsc) + bb.x, 0.f);
    r.y = fmaxf(di * (acc.y + s0.y * selfsc) + bb.y, 0.f);
    r.z = fmaxf(di * (acc.z + s1.x * selfsc) + bb.z, 0.f);
    r.w = fmaxf(di * (acc.w + s1.y * selfsc) + bb.w, 0.f);

    if (FINAL) {
        float4 lwv = *(const float4*)&lw[l4];
        float p = r.x * lwv.x + r.y * lwv.y + r.z * lwv.z + r.w * lwv.w;
        #pragma unroll
        for (int o = 16; o > 0; o >>= 1) p += __shfl_xor_sync(0xffffffffu, p, o);
        if (lane == 0) out[w] = p + lb[0];
    } else {
        __half2 h0 = __floats2half2_rn(r.x, r.y);
        __half2 h1 = __floats2half2_rn(r.z, r.w);
        uint2 u; u.x = *(uint32_t*)&h0; u.y = *(uint32_t*)&h1;
        *(uint2*)&g_h[w * DIM + l4] = u;
    }
}

// ---------------- launch ----------------

extern "C" void kernel_launch(void* const* d_in, const int* in_sizes, int n_in,
                              void* d_out, int out_size) {
    const float* x  = (const float*)d_in[0];
    const int*   ei = (const int*)d_in[1];
    const int*   src = ei;
    const int*   dst = ei + EE;
    const float* W0 = (const float*)d_in[2];
    const float* b0 = (const float*)d_in[3];
    const float* W1 = (const float*)d_in[4];
    const float* b1 = (const float*)d_in[5];
    const float* W2 = (const float*)d_in[6];
    const float* b2 = (const float*)d_in[7];
    const float* lw = (const float*)d_in[8];
    const float* lb = (const float*)d_in[9];
    float* out = (float*)d_out;

    static cudaStream_t s2 = nullptr;
    static cudaEvent_t evFork = nullptr, evCsr = nullptr;
    if (s2 == nullptr) {
        cudaStreamCreateWithFlags(&s2, cudaStreamNonBlocking);
        cudaEventCreateWithFlags(&evFork, cudaEventDisableTiming);
        cudaEventCreateWithFlags(&evCsr, cudaEventDisableTiming);
        cudaFuncSetAttribute(gemm_tc<false, false>, cudaFuncAttributeMaxDynamicSharedMemorySize, GEMM_SMEM);
        cudaFuncSetAttribute(gemm_tc<true, true>,   cudaFuncAttributeMaxDynamicSharedMemorySize, GEMM_SMEM);
    }

    const int GEMM_BLOCKS = (NN + 127) / 128;   // 313
    const int AGG_BLOCKS = (NN * 32) / 256;     // one warp per node

    // Fork: s2 builds the buckets (no zero pass needed: g_cnt is 0 on entry),
    // concurrent with stream 0's wconv + gemm0.
    cudaEventRecord(evFork, 0);
    cudaStreamWaitEvent(s2, evFork, 0);
    place_k<<<EE / 1024, 256, 0, s2>>>(src, dst);
    cudaEventRecord(evCsr, s2);

    wconv_k<<<48, 256>>>(W0, W1, W2);                                // W^T fp16 (all layers)
    gemm_tc<false, false><<<GEMM_BLOCKS, 256, GEMM_SMEM>>>(x, 0);    // hs0 = x @ W0 (unscaled)
    cudaStreamWaitEvent(0, evCsr, 0);                                // join before agg0

    // layer 0 (src-side dinv applied per edge via prefetched lanes)
    agg_k<true, false><<<AGG_BLOCKS, 256>>>(b0, nullptr, nullptr, nullptr);
    // layer 1
    gemm_tc<true, true><<<GEMM_BLOCKS, 256, GEMM_SMEM>>>(nullptr, 1);
    agg_k<false, false><<<AGG_BLOCKS, 256>>>(b1, nullptr, nullptr, nullptr);
    // layer 2 + final linear fused (also resets g_cnt for the next call)
    gemm_tc<true, true><<<GEMM_BLOCKS, 256, GEMM_SMEM>>>(nullptr, 2);
    agg_k<false, true><<<AGG_BLOCKS, 256>>>(b2, lw, lb, out);
}